// round 2
// baseline (speedup 1.0000x reference)
#include <cuda_runtime.h>
#include <cstdint>
#include <cstddef>

#define TSTEPS 512
#define BATCH  128

// 192MB scratch for the input projection (static device array: allowed).
__device__ float g_Gx[(size_t)BATCH * TSTEPS * 768];

// ---- f32x2 helpers ----
typedef unsigned long long ull;
__device__ __forceinline__ ull pack2(float x, float y) {
    ull u; asm("mov.b64 %0, {%1,%2};" : "=l"(u) : "f"(x), "f"(y)); return u;
}
__device__ __forceinline__ void unpack2(ull u, float& x, float& y) {
    asm("mov.b64 {%0,%1}, %2;" : "=f"(x), "=f"(y) : "l"(u));
}
__device__ __forceinline__ void fma2(ull& d, ull a, ull b) {
    asm("fma.rn.f32x2 %0, %1, %2, %0;" : "+l"(d) : "l"(a), "l"(b));
}

// ---- cluster helpers ----
__device__ __forceinline__ uint32_t smem_u32(const void* p) {
    uint32_t a;
    asm("{ .reg .u64 t; cvta.to.shared.u64 t, %1; cvt.u32.u64 %0, t; }" : "=r"(a) : "l"(p));
    return a;
}
__device__ __forceinline__ uint32_t mapa_rank(uint32_t addr, uint32_t rank) {
    uint32_t r; asm("mapa.shared::cluster.u32 %0, %1, %2;" : "=r"(r) : "r"(addr), "r"(rank));
    return r;
}
__device__ __forceinline__ void st_cluster_f32(uint32_t addr, float v) {
    asm volatile("st.shared::cluster.f32 [%0], %1;" :: "r"(addr), "f"(v));
}
__device__ __forceinline__ void cluster_sync() {
    asm volatile("barrier.cluster.arrive.aligned;" ::: "memory");
    asm volatile("barrier.cluster.wait.aligned;" ::: "memory");
}
__device__ __forceinline__ uint32_t cluster_rank() {
    uint32_t r; asm("mov.u32 %0, %%cluster_ctarank;" : "=r"(r)); return r;
}

// ============================================================================
// Stage 1: Gx[m][gate*256+n] = x[m] @ W[:256] + b.  BM=128 BN=64 BK=16.
// grid (512, 12): 12 nTiles = 3 gates x 4 tiles of 64.
// ============================================================================
__global__ __launch_bounds__(256) void proj_kernel(
    const float* __restrict__ x,
    const float* __restrict__ Wr, const float* __restrict__ br,
    const float* __restrict__ Wz, const float* __restrict__ bz,
    const float* __restrict__ Wc, const float* __restrict__ bc)
{
    const int mTile = blockIdx.x, nTile = blockIdx.y;
    const int gate = nTile >> 2, nGateBase = (nTile & 3) * 64;
    const float* W    = (gate == 0) ? Wr : ((gate == 1) ? Wz : Wc);
    const float* bias = (gate == 0) ? br : ((gate == 1) ? bz : bc);

    __shared__ float As[16][132];   // [k][m]
    __shared__ float Ws[16][64];    // [k][n]

    const int tid = threadIdx.x;
    const int tx = tid & 15, ty = tid >> 4;   // 16 col-groups x 16 row-groups
    const int mBase = mTile * 128;

    ull acc[4][4];                  // [rowpair][col]
    #pragma unroll
    for (int i = 0; i < 4; i++)
        #pragma unroll
        for (int jj = 0; jj < 4; jj++) acc[i][jj] = 0ull;

    float bv[4];
    #pragma unroll
    for (int jj = 0; jj < 4; jj++) bv[jj] = bias[nGateBase + tx * 4 + jj];

    for (int k0 = 0; k0 < 256; k0 += 16) {
        __syncthreads();
        #pragma unroll
        for (int q = 0; q < 2; q++) {
            int idx = tid + q * 256, row = idx >> 2, c4 = idx & 3;
            float4 v = *reinterpret_cast<const float4*>(
                &x[(size_t)(mBase + row) * 256 + k0 + c4 * 4]);
            As[c4 * 4 + 0][row] = v.x; As[c4 * 4 + 1][row] = v.y;
            As[c4 * 4 + 2][row] = v.z; As[c4 * 4 + 3][row] = v.w;
        }
        {
            int k = tid >> 4, n4 = (tid & 15) * 4;
            *reinterpret_cast<float4*>(&Ws[k][n4]) =
                *reinterpret_cast<const float4*>(&W[(size_t)(k0 + k) * 256 + nGateBase + n4]);
        }
        __syncthreads();

        #pragma unroll
        for (int k = 0; k < 16; k++) {
            const ull* ap = reinterpret_cast<const ull*>(&As[k][ty * 8]);
            ull a0 = ap[0], a1 = ap[1], a2 = ap[2], a3 = ap[3];
            #pragma unroll
            for (int jj = 0; jj < 4; jj++) {
                float w = Ws[k][tx * 4 + jj];
                ull w2 = pack2(w, w);
                fma2(acc[0][jj], a0, w2); fma2(acc[1][jj], a1, w2);
                fma2(acc[2][jj], a2, w2); fma2(acc[3][jj], a3, w2);
            }
        }
    }

    const int nOut = gate * 256 + nGateBase + tx * 4;
    #pragma unroll
    for (int rp = 0; rp < 4; rp++) {
        float r0[4], r1[4];
        #pragma unroll
        for (int jj = 0; jj < 4; jj++) {
            unpack2(acc[rp][jj], r0[jj], r1[jj]);
            r0[jj] += bv[jj]; r1[jj] += bv[jj];
        }
        int m0 = mBase + ty * 8 + rp * 2;
        *reinterpret_cast<float4*>(&g_Gx[(size_t)m0 * 768 + nOut]) =
            make_float4(r0[0], r0[1], r0[2], r0[3]);
        *reinterpret_cast<float4*>(&g_Gx[(size_t)(m0 + 1) * 768 + nOut]) =
            make_float4(r1[0], r1[1], r1[2], r1[3]);
    }
}

// ============================================================================
// Stage 2: recurrence. 16 clusters x 8 CTAs; cluster owns 8 batch rows;
// CTA rank j owns output cols [32j,32j+32) of each gate; recurrent weights
// (h-part, transposed) resident in SMEM. h / r*h exchanged via DSMEM.
// ============================================================================
struct RecSmem {
    float wrz[64][261];     // [c][k]: c<32 -> Wr, c>=32 -> Wz (stride 261: conflict-free)
    float wc[32][261];
    float hT[256][8];       // h transposed: [k][row] (peers push h_new here)
    float rhT[256][8];      // r*h transposed (peers push here)
    float h_own[8][32];     // own slice of h, [row][c]
    float z_s[8][32];
    float red1[4][8][64];   // phase1 split-K partials [kg][row][c]
    float red2[8][8][32];   // phase2 split-K partials
};

__global__ __launch_bounds__(256, 1) __cluster_dims__(8, 1, 1)
void rec_kernel(const float* __restrict__ h0,
                const float* __restrict__ Wr,
                const float* __restrict__ Wz,
                const float* __restrict__ Wc,
                float* __restrict__ out)
{
    extern __shared__ char smem_raw[];
    RecSmem& S = *reinterpret_cast<RecSmem*>(smem_raw);

    const int tid = threadIdx.x;
    const int j = (int)cluster_rank();       // 0..7
    const int b0 = (blockIdx.x >> 3) * 8;    // first batch row of cluster

    // ---- init: weights (rows 256..511 of W = h-part), h state ----
    {
        const int lane = tid & 31, w = tid >> 5;
        for (int k = w; k < 256; k += 8) {
            S.wrz[lane][k]      = Wr[(size_t)(256 + k) * 256 + j * 32 + lane];
            S.wrz[32 + lane][k] = Wz[(size_t)(256 + k) * 256 + j * 32 + lane];
            S.wc[lane][k]       = Wc[(size_t)(256 + k) * 256 + j * 32 + lane];
        }
    }
    for (int idx = tid; idx < 8 * 256; idx += 256) {
        int r = idx >> 8, k = idx & 255;
        S.hT[k][r] = h0[(size_t)(b0 + r) * 256 + k];
    }
    for (int idx = tid; idx < 8 * 32; idx += 256) {
        int r = idx >> 5, c = idx & 31;
        S.h_own[r][c] = h0[(size_t)(b0 + r) * 256 + j * 32 + c];
    }
    __syncthreads();
    cluster_sync();   // everyone's hT init done before any remote h pushes

    uint32_t rh_local = smem_u32(&S.rhT[0][0]);
    uint32_t hT_local = smem_u32(&S.hT[0][0]);
    uint32_t peer_rh[8], peer_hT[8];
    #pragma unroll
    for (int rk = 0; rk < 8; rk++) {
        peer_rh[rk] = mapa_rank(rh_local, (uint32_t)rk);
        peer_hT[rk] = mapa_rank(hT_local, (uint32_t)rk);
    }

    // thread roles
    const int c1  = tid & 63, kg1 = tid >> 6;   // phase1: col (r|z), k-group of 64
    const int c2  = tid & 31, kg2 = tid >> 5;   // phase2: col, k-group of 32
    const int e1r = tid >> 6;                    // epi1 rows e1r and e1r+4, col c1
    const int e2r = tid >> 5;                    // epi2 row, col c2

    #pragma unroll 1
    for (int t = 0; t < TSTEPS; t++) {
        // prefetch Gx (used in epilogues)
        const int g1 = (c1 < 32) ? 0 : 1, col1 = j * 32 + (c1 & 31);
        float gxA = g_Gx[((size_t)(b0 + e1r) * TSTEPS + t) * 768 + g1 * 256 + col1];
        float gxB = g_Gx[((size_t)(b0 + e1r + 4) * TSTEPS + t) * 768 + g1 * 256 + col1];
        float gxC = g_Gx[((size_t)(b0 + e2r) * TSTEPS + t) * 768 + 512 + j * 32 + c2];

        // -- phase 1: h @ Wh_{r,z}; split-K over 4 groups of 64 --
        {
            ull acc[4] = {0ull, 0ull, 0ull, 0ull};  // row pairs (0,1)(2,3)(4,5)(6,7)
            const int kb = kg1 * 64;
            #pragma unroll 8
            for (int kk = 0; kk < 64; kk++) {
                float w = S.wrz[c1][kb + kk];
                ull w2 = pack2(w, w);
                const ull* hp = reinterpret_cast<const ull*>(&S.hT[kb + kk][0]);
                fma2(acc[0], hp[0], w2); fma2(acc[1], hp[1], w2);
                fma2(acc[2], hp[2], w2); fma2(acc[3], hp[3], w2);
            }
            #pragma unroll
            for (int p = 0; p < 4; p++) {
                float a, b; unpack2(acc[p], a, b);
                S.red1[kg1][2 * p][c1] = a; S.red1[kg1][2 * p + 1][c1] = b;
            }
        }
        __syncthreads();

        // -- epilogue 1: r/z gates; push r*h to all peers --
        {
            const int rB = e1r + 4;
            float sA = S.red1[0][e1r][c1] + S.red1[1][e1r][c1]
                     + S.red1[2][e1r][c1] + S.red1[3][e1r][c1] + gxA;
            float sB = S.red1[0][rB][c1] + S.red1[1][rB][c1]
                     + S.red1[2][rB][c1] + S.red1[3][rB][c1] + gxB;
            float vA = 1.0f / (1.0f + expf(-sA));
            float vB = 1.0f / (1.0f + expf(-sB));
            if (c1 < 32) {   // r gate -> r*h, scatter to every CTA's rhT[k][row]
                float rhA = vA * S.h_own[e1r][c1];
                float rhB = vB * S.h_own[rB][c1];
                uint32_t offA = (uint32_t)(((j * 32 + c1) * 8 + e1r) * 4);
                uint32_t offB = (uint32_t)(((j * 32 + c1) * 8 + rB) * 4);
                #pragma unroll
                for (int rk = 0; rk < 8; rk++) {
                    st_cluster_f32(peer_rh[rk] + offA, rhA);
                    st_cluster_f32(peer_rh[rk] + offB, rhB);
                }
            } else {         // z gate
                S.z_s[e1r][c1 - 32] = vA;
                S.z_s[rB][c1 - 32] = vB;
            }
        }
        cluster_sync();

        // -- phase 2: (r*h) @ Wh_c; split-K over 8 groups of 32 --
        {
            ull acc[4] = {0ull, 0ull, 0ull, 0ull};
            const int kb = kg2 * 32;
            #pragma unroll 8
            for (int kk = 0; kk < 32; kk++) {
                float w = S.wc[c2][kb + kk];
                ull w2 = pack2(w, w);
                const ull* hp = reinterpret_cast<const ull*>(&S.rhT[kb + kk][0]);
                fma2(acc[0], hp[0], w2); fma2(acc[1], hp[1], w2);
                fma2(acc[2], hp[2], w2); fma2(acc[3], hp[3], w2);
            }
            #pragma unroll
            for (int p = 0; p < 4; p++) {
                float a, b; unpack2(acc[p], a, b);
                S.red2[kg2][2 * p][c2] = a; S.red2[kg2][2 * p + 1][c2] = b;
            }
        }
        __syncthreads();

        // -- epilogue 2: candidate, h update, output, push h_new --
        {
            float s = gxC;
            #pragma unroll
            for (int g = 0; g < 8; g++) s += S.red2[g][e2r][c2];
            float cv = tanhf(s);
            float z = S.z_s[e2r][c2];
            float hold = S.h_own[e2r][c2];
            float hn = hold + z * (cv - hold);
            S.h_own[e2r][c2] = hn;
            out[((size_t)(b0 + e2r) * TSTEPS + t) * 256 + j * 32 + c2] = hn;
            uint32_t off = (uint32_t)(((j * 32 + c2) * 8 + e2r) * 4);
            #pragma unroll
            for (int rk = 0; rk < 8; rk++)
                st_cluster_f32(peer_hT[rk] + off, hn);
        }
        cluster_sync();
    }
}

extern "C" void kernel_launch(void* const* d_in, const int* in_sizes, int n_in,
                              void* d_out, int out_size) {
    const float* x  = (const float*)d_in[0];
    const float* h0 = (const float*)d_in[1];
    const float* Wr = (const float*)d_in[2];
    const float* br = (const float*)d_in[3];
    const float* Wz = (const float*)d_in[4];
    const float* bz = (const float*)d_in[5];
    const float* Wc = (const float*)d_in[6];
    const float* bc = (const float*)d_in[7];
    float* out = (float*)d_out;

    static bool attr_set = false;
    if (!attr_set) {
        cudaFuncSetAttribute(rec_kernel, cudaFuncAttributeMaxDynamicSharedMemorySize,
                             (int)sizeof(RecSmem));
        attr_set = true;
    }

    proj_kernel<<<dim3(512, 12), 256>>>(x, Wr, br, Wz, bz, Wc, bc);
    rec_kernel<<<128, 256, sizeof(RecSmem)>>>(h0, Wr, Wz, Wc, out);
}

// round 3
// speedup vs baseline: 1.6521x; 1.6521x over previous
#include <cuda_runtime.h>
#include <cstdint>
#include <cstddef>

#define TSTEPS 512
#define BATCH  128

// 192MB scratch for the input projection (static device array: allowed).
__device__ float g_Gx[(size_t)BATCH * TSTEPS * 768];

// ---- f32x2 helpers ----
typedef unsigned long long ull;
__device__ __forceinline__ ull pack2(float x, float y) {
    ull u; asm("mov.b64 %0, {%1,%2};" : "=l"(u) : "f"(x), "f"(y)); return u;
}
__device__ __forceinline__ void unpack2(ull u, float& x, float& y) {
    asm("mov.b64 {%0,%1}, %2;" : "=f"(x), "=f"(y) : "l"(u));
}
__device__ __forceinline__ void fma2(ull& d, ull a, ull b) {
    asm("fma.rn.f32x2 %0, %1, %2, %0;" : "+l"(d) : "l"(a), "l"(b));
}
__device__ __forceinline__ ull add2(ull a, ull b) {
    ull d; asm("add.rn.f32x2 %0, %1, %2;" : "=l"(d) : "l"(a), "l"(b)); return d;
}

// ---- cluster helpers ----
__device__ __forceinline__ uint32_t smem_u32(const void* p) {
    uint32_t a;
    asm("{ .reg .u64 t; cvta.to.shared.u64 t, %1; cvt.u32.u64 %0, t; }" : "=r"(a) : "l"(p));
    return a;
}
__device__ __forceinline__ uint32_t mapa_rank(uint32_t addr, uint32_t rank) {
    uint32_t r; asm("mapa.shared::cluster.u32 %0, %1, %2;" : "=r"(r) : "r"(addr), "r"(rank));
    return r;
}
__device__ __forceinline__ void st_cluster_u64(uint32_t addr, ull v) {
    asm volatile("st.shared::cluster.b64 [%0], %1;" :: "r"(addr), "l"(v));
}
__device__ __forceinline__ void cluster_sync() {
    asm volatile("barrier.cluster.arrive.aligned;" ::: "memory");
    asm volatile("barrier.cluster.wait.aligned;" ::: "memory");
}
__device__ __forceinline__ uint32_t cluster_rank() {
    uint32_t r; asm("mov.u32 %0, %%cluster_ctarank;" : "=r"(r)); return r;
}

// fast activations (MUFU-based, err ~1e-6)
__device__ __forceinline__ float fast_sigmoid(float x) {
    return __fdividef(1.0f, 1.0f + __expf(-x));
}
__device__ __forceinline__ float fast_tanh(float x) {
    return 2.0f * __fdividef(1.0f, 1.0f + __expf(-2.0f * x)) - 1.0f;
}

// ============================================================================
// Stage 1: Gx[m][gate*256+n] = x[m] @ W[:256] + b.  BM=128 BN=64 BK=16.
// ============================================================================
__global__ __launch_bounds__(256) void proj_kernel(
    const float* __restrict__ x,
    const float* __restrict__ Wr, const float* __restrict__ br,
    const float* __restrict__ Wz, const float* __restrict__ bz,
    const float* __restrict__ Wc, const float* __restrict__ bc)
{
    const int mTile = blockIdx.x, nTile = blockIdx.y;
    const int gate = nTile >> 2, nGateBase = (nTile & 3) * 64;
    const float* W    = (gate == 0) ? Wr : ((gate == 1) ? Wz : Wc);
    const float* bias = (gate == 0) ? br : ((gate == 1) ? bz : bc);

    __shared__ float As[16][132];
    __shared__ float Ws[16][64];

    const int tid = threadIdx.x;
    const int tx = tid & 15, ty = tid >> 4;
    const int mBase = mTile * 128;

    ull acc[4][4];
    #pragma unroll
    for (int i = 0; i < 4; i++)
        #pragma unroll
        for (int jj = 0; jj < 4; jj++) acc[i][jj] = 0ull;

    float bv[4];
    #pragma unroll
    for (int jj = 0; jj < 4; jj++) bv[jj] = bias[nGateBase + tx * 4 + jj];

    for (int k0 = 0; k0 < 256; k0 += 16) {
        __syncthreads();
        #pragma unroll
        for (int q = 0; q < 2; q++) {
            int idx = tid + q * 256, row = idx >> 2, c4 = idx & 3;
            float4 v = *reinterpret_cast<const float4*>(
                &x[(size_t)(mBase + row) * 256 + k0 + c4 * 4]);
            As[c4 * 4 + 0][row] = v.x; As[c4 * 4 + 1][row] = v.y;
            As[c4 * 4 + 2][row] = v.z; As[c4 * 4 + 3][row] = v.w;
        }
        {
            int k = tid >> 4, n4 = (tid & 15) * 4;
            *reinterpret_cast<float4*>(&Ws[k][n4]) =
                *reinterpret_cast<const float4*>(&W[(size_t)(k0 + k) * 256 + nGateBase + n4]);
        }
        __syncthreads();

        #pragma unroll
        for (int k = 0; k < 16; k++) {
            const ull* ap = reinterpret_cast<const ull*>(&As[k][ty * 8]);
            ull a0 = ap[0], a1 = ap[1], a2 = ap[2], a3 = ap[3];
            #pragma unroll
            for (int jj = 0; jj < 4; jj++) {
                float w = Ws[k][tx * 4 + jj];
                ull w2 = pack2(w, w);
                fma2(acc[0][jj], a0, w2); fma2(acc[1][jj], a1, w2);
                fma2(acc[2][jj], a2, w2); fma2(acc[3][jj], a3, w2);
            }
        }
    }

    const int nOut = gate * 256 + nGateBase + tx * 4;
    #pragma unroll
    for (int rp = 0; rp < 4; rp++) {
        float r0[4], r1[4];
        #pragma unroll
        for (int jj = 0; jj < 4; jj++) {
            unpack2(acc[rp][jj], r0[jj], r1[jj]);
            r0[jj] += bv[jj]; r1[jj] += bv[jj];
        }
        int m0 = mBase + ty * 8 + rp * 2;
        *reinterpret_cast<float4*>(&g_Gx[(size_t)m0 * 768 + nOut]) =
            make_float4(r0[0], r0[1], r0[2], r0[3]);
        *reinterpret_cast<float4*>(&g_Gx[(size_t)(m0 + 1) * 768 + nOut]) =
            make_float4(r1[0], r1[1], r1[2], r1[3]);
    }
}

// ============================================================================
// Stage 2: recurrence. 16 clusters x 8 CTAs; cluster owns 8 batch rows;
// CTA rank j owns cols [32j,32j+32) per gate. Recurrent weights in REGISTERS.
// h / r*h exchanged via DSMEM row-pair b64 pushes.
// ============================================================================
struct RecSmem {
    float hT[256][8];    // h transposed [k][row]; peers push h_new here
    float rhT[256][8];   // r*h transposed; peers push here
    ull   z_s2[4][32];   // z gate, row-pairs
    ull   red[2048];     // split-K partials (phase1: [8][4][64], phase2: [16][4][32])
};
__shared__ RecSmem S;

__global__ __launch_bounds__(256, 1) __cluster_dims__(8, 1, 1)
void rec_kernel(const float* __restrict__ h0,
                const float* __restrict__ Wr,
                const float* __restrict__ Wz,
                const float* __restrict__ Wc,
                float* __restrict__ out)
{
    const int tid = threadIdx.x;
    const int j = (int)cluster_rank();       // 0..7
    const int b0 = (blockIdx.x >> 3) * 8;    // first batch row of cluster

    // ---- thread roles ----
    const int cg1 = tid & 31, kg1 = tid >> 5;   // phase1: col pair {2cg1,2cg1+1}, 32-k group
    const int cg2 = tid & 15, kg2 = tid >> 4;   // phase2: col pair {2cg2,2cg2+1}, 16-k group
    const int e1c = tid & 63, e1rp = tid >> 6;  // epi1: col, row-pair
    const int e2c = tid & 31, e2rp = (tid >> 5) & 3;  // epi2 (tid<128): col, row-pair

    // ---- register-resident weights (loop-invariant) ----
    float w1[32][2];   // phase1: Wr or Wz, rows kg1*32.., cols {2cg1,2cg1+1} (mod gate)
    {
        const float* Wsel = (cg1 < 16) ? Wr : Wz;
        const int colb = j * 32 + ((2 * cg1) & 31);
        #pragma unroll
        for (int kk = 0; kk < 32; kk++) {
            const float* row = &Wsel[(size_t)(256 + kg1 * 32 + kk) * 256 + colb];
            w1[kk][0] = row[0]; w1[kk][1] = row[1];
        }
    }
    float w2[16][2];   // phase2: Wc rows kg2*16.., cols {2cg2,2cg2+1}
    {
        const int colb = j * 32 + 2 * cg2;
        #pragma unroll
        for (int kk = 0; kk < 16; kk++) {
            const float* row = &Wc[(size_t)(256 + kg2 * 16 + kk) * 256 + colb];
            w2[kk][0] = row[0]; w2[kk][1] = row[1];
        }
    }

    // ---- init h state ----
    for (int idx = tid; idx < 8 * 256; idx += 256) {
        int r = idx >> 8, k = idx & 255;
        S.hT[k][r] = h0[(size_t)(b0 + r) * 256 + k];
    }
    __syncthreads();
    cluster_sync();

    // ---- peer DSMEM addresses ----
    uint32_t rh_local = smem_u32(&S.rhT[0][0]);
    uint32_t hT_local = smem_u32(&S.hT[0][0]);
    uint32_t peer_rh[8], peer_hT[8];
    #pragma unroll
    for (int rk = 0; rk < 8; rk++) {
        peer_rh[rk] = mapa_rank(rh_local, (uint32_t)rk);
        peer_hT[rk] = mapa_rank(hT_local, (uint32_t)rk);
    }

    // ---- Gx prefetch (software pipeline: cur used this step, nxt loaded for t+1) ----
    const int g1 = (e1c < 32) ? 0 : 1;
    const size_t gx1A = (size_t)(b0 + 2 * e1rp)     * TSTEPS * 768 + g1 * 256 + j * 32 + (e1c & 31);
    const size_t gx1B = (size_t)(b0 + 2 * e1rp + 1) * TSTEPS * 768 + g1 * 256 + j * 32 + (e1c & 31);
    const size_t gx2A = (size_t)(b0 + 2 * e2rp)     * TSTEPS * 768 + 512 + j * 32 + e2c;
    const size_t gx2B = (size_t)(b0 + 2 * e2rp + 1) * TSTEPS * 768 + 512 + j * 32 + e2c;

    float cA = g_Gx[gx1A], cB = g_Gx[gx1B];
    float cCA = g_Gx[gx2A], cCB = g_Gx[gx2B];

    const int kb1 = kg1 * 32, kb2 = kg2 * 16;

    #pragma unroll 1
    for (int t = 0; t < TSTEPS; t++) {
        // prefetch next step's Gx (consumed next iteration)
        const size_t tn = (size_t)((t + 1 < TSTEPS) ? t + 1 : t) * 768;
        float nA = g_Gx[gx1A + tn], nB = g_Gx[gx1B + tn];
        float nCA = g_Gx[gx2A + tn], nCB = g_Gx[gx2B + tn];

        // -- phase 1: h @ Wh_{r,z}; 2 cols x 8 rows per thread, 32 k --
        {
            ull acc[8];
            #pragma unroll
            for (int p = 0; p < 8; p++) acc[p] = 0ull;
            #pragma unroll
            for (int kk = 0; kk < 32; kk++) {
                const ulonglong2* hp =
                    reinterpret_cast<const ulonglong2*>(&S.hT[kb1 + kk][0]);
                ulonglong2 p0 = hp[0], p1 = hp[1];
                ull wa = pack2(w1[kk][0], w1[kk][0]);
                ull wb = pack2(w1[kk][1], w1[kk][1]);
                fma2(acc[0], p0.x, wa); fma2(acc[1], p0.y, wa);
                fma2(acc[2], p1.x, wa); fma2(acc[3], p1.y, wa);
                fma2(acc[4], p0.x, wb); fma2(acc[5], p0.y, wb);
                fma2(acc[6], p1.x, wb); fma2(acc[7], p1.y, wb);
            }
            #pragma unroll
            for (int rp = 0; rp < 4; rp++) {
                ulonglong2 v; v.x = acc[rp]; v.y = acc[rp + 4];
                *reinterpret_cast<ulonglong2*>(
                    &S.red[(size_t)(kg1 * 4 + rp) * 64 + 2 * cg1]) = v;
            }
        }
        __syncthreads();

        // -- epilogue 1: sigmoid gates; push r*h row-pairs to all peers --
        {
            ull s = S.red[(size_t)e1rp * 64 + e1c];
            #pragma unroll
            for (int g = 1; g < 8; g++)
                s = add2(s, S.red[(size_t)(g * 4 + e1rp) * 64 + e1c]);
            float lo, hi; unpack2(s, lo, hi);
            float vA = fast_sigmoid(lo + cA);
            float vB = fast_sigmoid(hi + cB);
            if (e1c < 32) {
                // r gate: r*h for rows {2rp, 2rp+1}, col k = j*32+e1c
                ull h2 = *reinterpret_cast<const ull*>(&S.hT[j * 32 + e1c][2 * e1rp]);
                float hA, hB; unpack2(h2, hA, hB);
                ull rh2 = pack2(vA * hA, vB * hB);
                uint32_t off = (uint32_t)(((j * 32 + e1c) * 8 + 2 * e1rp) * 4);
                #pragma unroll
                for (int rk = 0; rk < 8; rk++)
                    st_cluster_u64(peer_rh[rk] + off, rh2);
            } else {
                S.z_s2[e1rp][e1c - 32] = pack2(vA, vB);
            }
        }
        cluster_sync();

        // -- phase 2: (r*h) @ Wh_c; 2 cols x 8 rows per thread, 16 k --
        {
            ull acc[8];
            #pragma unroll
            for (int p = 0; p < 8; p++) acc[p] = 0ull;
            #pragma unroll
            for (int kk = 0; kk < 16; kk++) {
                const ulonglong2* hp =
                    reinterpret_cast<const ulonglong2*>(&S.rhT[kb2 + kk][0]);
                ulonglong2 p0 = hp[0], p1 = hp[1];
                ull wa = pack2(w2[kk][0], w2[kk][0]);
                ull wb = pack2(w2[kk][1], w2[kk][1]);
                fma2(acc[0], p0.x, wa); fma2(acc[1], p0.y, wa);
                fma2(acc[2], p1.x, wa); fma2(acc[3], p1.y, wa);
                fma2(acc[4], p0.x, wb); fma2(acc[5], p0.y, wb);
                fma2(acc[6], p1.x, wb); fma2(acc[7], p1.y, wb);
            }
            #pragma unroll
            for (int rp = 0; rp < 4; rp++) {
                ulonglong2 v; v.x = acc[rp]; v.y = acc[rp + 4];
                *reinterpret_cast<ulonglong2*>(
                    &S.red[(size_t)(kg2 * 4 + rp) * 32 + 2 * cg2]) = v;
            }
        }
        __syncthreads();

        // -- epilogue 2 (threads 0..127): candidate, h update, output, push h --
        if (tid < 128) {
            ull s = S.red[(size_t)e2rp * 32 + e2c];
            #pragma unroll
            for (int g = 1; g < 16; g++)
                s = add2(s, S.red[(size_t)(g * 4 + e2rp) * 32 + e2c]);
            float lo, hi; unpack2(s, lo, hi);
            float tA = fast_tanh(lo + cCA);
            float tB = fast_tanh(hi + cCB);
            float zA, zB; unpack2(S.z_s2[e2rp][e2c], zA, zB);
            ull h2 = *reinterpret_cast<const ull*>(&S.hT[j * 32 + e2c][2 * e2rp]);
            float hA, hB; unpack2(h2, hA, hB);
            float hnA = hA + zA * (tA - hA);
            float hnB = hB + zB * (tB - hB);
            out[((size_t)(b0 + 2 * e2rp) * TSTEPS + t) * 256 + j * 32 + e2c] = hnA;
            out[((size_t)(b0 + 2 * e2rp + 1) * TSTEPS + t) * 256 + j * 32 + e2c] = hnB;
            ull hn2 = pack2(hnA, hnB);
            uint32_t off = (uint32_t)(((j * 32 + e2c) * 8 + 2 * e2rp) * 4);
            #pragma unroll
            for (int rk = 0; rk < 8; rk++)
                st_cluster_u64(peer_hT[rk] + off, hn2);
        }
        cluster_sync();

        cA = nA; cB = nB; cCA = nCA; cCB = nCB;
    }
}

extern "C" void kernel_launch(void* const* d_in, const int* in_sizes, int n_in,
                              void* d_out, int out_size) {
    const float* x  = (const float*)d_in[0];
    const float* h0 = (const float*)d_in[1];
    const float* Wr = (const float*)d_in[2];
    const float* br = (const float*)d_in[3];
    const float* Wz = (const float*)d_in[4];
    const float* bz = (const float*)d_in[5];
    const float* Wc = (const float*)d_in[6];
    const float* bc = (const float*)d_in[7];
    float* out = (float*)d_out;

    proj_kernel<<<dim3(512, 12), 256>>>(x, Wr, br, Wz, bz, Wc, bc);
    rec_kernel<<<128, 256>>>(h0, Wr, Wz, Wc, out);
}